// round 1
// baseline (speedup 1.0000x reference)
#include <cuda_runtime.h>
#include <math.h>

#define Bc   4
#define Nc   4096
#define Kc   20
#define BN   (Bc*Nc)          // 16384
#define VEPS 1e-6f
#define BNEPS 1e-5f

// ---------------- persistent device scratch (no allocations allowed) -------
__device__ int   g_idx[Bc*Nc*Kc];
__device__ float g_bufA[BN*3*128];
__device__ float g_bufB[BN*3*128];
__device__ float g_p[BN*3*128];
__device__ float g_d[BN*3*128];
__device__ float g_s1[128];          // block1 norm sums  (sum, sum2)
__device__ float g_s2[128];
__device__ float g_s3[128];
__device__ float g_s4[256];
__device__ float g_s5[2048];         // conv5 norm sums (1024 + 1024)
__device__ float g_sumv [Bc*1024*3];
__device__ float g_sumvn[Bc*1024*3];
__device__ float g_mu[1024];
__device__ float g_rstd[1024];

// ---------------------------------------------------------------------------
__global__ void zero_stats() {
    int i = blockIdx.x * 256 + threadIdx.x;          // grid 48*256 = 12288
    if (i < 128) { g_s1[i] = 0.f; g_s2[i] = 0.f; g_s3[i] = 0.f; }
    if (i < 256) { g_s4[i] = 0.f; }
    if (i < 2048){ g_s5[i] = 0.f; }
    g_sumv[i]  = 0.f;
    g_sumvn[i] = 0.f;
}

// --------------------------- KNN (top-20 by -dist) --------------------------
// 2 queries per block, 256 threads. dist kept in smem; 20 rounds of argmax
// with JAX tie-break (equal value -> lower index).
__global__ __launch_bounds__(256) void knn_kernel(const float* __restrict__ x) {
    int b  = blockIdx.y;
    int n0 = blockIdx.x * 2;
    __shared__ float dist[2][Nc];
    __shared__ float rv[256];
    __shared__ int   ri[256];
    const float* xb = x + (size_t)b * Nc * 3;

    float q0x = xb[n0*3+0],     q0y = xb[n0*3+1],     q0z = xb[n0*3+2];
    float q1x = xb[(n0+1)*3+0], q1y = xb[(n0+1)*3+1], q1z = xb[(n0+1)*3+2];
    float sq0 = q0x*q0x + q0y*q0y + q0z*q0z;
    float sq1 = q1x*q1x + q1y*q1y + q1z*q1z;

    for (int j = threadIdx.x; j < Nc; j += 256) {
        float ax = xb[j*3+0], ay = xb[j*3+1], az = xb[j*3+2];
        float sqj = ax*ax + ay*ay + az*az;
        dist[0][j] = 2.f*(q0x*ax + q0y*ay + q0z*az) - sq0 - sqj;
        dist[1][j] = 2.f*(q1x*ax + q1y*ay + q1z*az) - sq1 - sqj;
    }
    __syncthreads();

    int half = threadIdx.x >> 7;       // 0/1 -> which query
    int lt   = threadIdx.x & 127;
    float* dh = dist[half];
    int n = n0 + half;

    for (int k = 0; k < Kc; k++) {
        float best = -3.3e38f; int bi = Nc;
        for (int j = lt; j < Nc; j += 128) {
            float v = dh[j];
            if (v > best) { best = v; bi = j; }    // ascending scan keeps lowest idx on tie
        }
        rv[threadIdx.x] = best; ri[threadIdx.x] = bi;
        __syncthreads();
        #pragma unroll
        for (int s = 64; s > 0; s >>= 1) {
            if (lt < s) {
                float ov = rv[threadIdx.x + s]; int oi = ri[threadIdx.x + s];
                float mv = rv[threadIdx.x];     int mi = ri[threadIdx.x];
                if (ov > mv || (ov == mv && oi < mi)) { rv[threadIdx.x] = ov; ri[threadIdx.x] = oi; }
            }
            __syncthreads();
        }
        if (lt == 0) {
            int w = ri[threadIdx.x];
            g_idx[((size_t)b*Nc + n)*Kc + k] = w;
            dh[w] = -3.4e38f;
        }
        __syncthreads();
    }
}

// --------------------------- block1 (3ch edge feat -> 64) -------------------
// block handles 2 points; f[2][20][9] built cooperatively in smem.
__device__ __forceinline__ void build_f(const float* __restrict__ x, int b, int n0,
                                        float f[2][Kc][9]) {
    int t = threadIdx.x;
    if (t < 2*Kc) {
        int ln = t / Kc, k = t % Kc;
        int n = n0 + ln;
        const float* xb = x + (size_t)b * Nc * 3;
        float cx = xb[n*3+0], cy = xb[n*3+1], cz = xb[n*3+2];
        int j = g_idx[((size_t)b*Nc + n)*Kc + k];
        float ax = xb[j*3+0], ay = xb[j*3+1], az = xb[j*3+2];
        f[ln][k][0] = ax - cx; f[ln][k][1] = ay - cy; f[ln][k][2] = az - cz;
        f[ln][k][3] = cx;      f[ln][k][4] = cy;      f[ln][k][5] = cz;
        // cross(nbr, ctr)
        f[ln][k][6] = ay*cz - az*cy;
        f[ln][k][7] = az*cx - ax*cz;
        f[ln][k][8] = ax*cy - ay*cx;
    }
}

__global__ __launch_bounds__(128) void block1_stats(const float* __restrict__ x,
                                                    const float* __restrict__ W1) {
    int b = blockIdx.y, n0 = blockIdx.x * 2;
    __shared__ float f[2][Kc][9];
    build_f(x, b, n0, f);
    __syncthreads();
    int t = threadIdx.x;
    int ln = t >> 6, c = t & 63;
    float w0 = W1[c*3+0], w1 = W1[c*3+1], w2 = W1[c*3+2];
    float sn = 0.f, sn2 = 0.f;
    #pragma unroll
    for (int k = 0; k < Kc; k++) {
        const float* fk = f[ln][k];
        float p0 = w0*fk[0] + w1*fk[3] + w2*fk[6];
        float p1 = w0*fk[1] + w1*fk[4] + w2*fk[7];
        float p2 = w0*fk[2] + w1*fk[5] + w2*fk[8];
        float nr = sqrtf(p0*p0 + p1*p1 + p2*p2) + VEPS;
        sn += nr; sn2 += nr*nr;
    }
    atomicAdd(&g_s1[c], sn);
    atomicAdd(&g_s1[64 + c], sn2);
}

__global__ __launch_bounds__(128) void block1_apply(const float* __restrict__ x,
                                                    const float* __restrict__ W1,
                                                    const float* __restrict__ D1,
                                                    const float* __restrict__ g1,
                                                    const float* __restrict__ b1) {
    int b = blockIdx.y, n0 = blockIdx.x * 2;
    __shared__ float f[2][Kc][9];
    build_f(x, b, n0, f);
    __syncthreads();
    int t = threadIdx.x;
    int ln = t >> 6, c = t & 63;
    float w0 = W1[c*3+0], w1 = W1[c*3+1], w2 = W1[c*3+2];
    float e0 = D1[c*3+0], e1 = D1[c*3+1], e2 = D1[c*3+2];
    float ga = g1[c], be = b1[c], mu = g_mu[c], rs = g_rstd[c];
    float a0 = 0.f, a1 = 0.f, a2 = 0.f;
    #pragma unroll
    for (int k = 0; k < Kc; k++) {
        const float* fk = f[ln][k];
        float p0 = w0*fk[0] + w1*fk[3] + w2*fk[6];
        float p1 = w0*fk[1] + w1*fk[4] + w2*fk[7];
        float p2 = w0*fk[2] + w1*fk[5] + w2*fk[8];
        float nr = sqrtf(p0*p0 + p1*p1 + p2*p2) + VEPS;
        float sc = (ga*(nr - mu)*rs + be) / nr;
        p0 *= sc; p1 *= sc; p2 *= sc;
        float d0 = e0*fk[0] + e1*fk[3] + e2*fk[6];
        float d1 = e0*fk[1] + e1*fk[4] + e2*fk[7];
        float d2 = e0*fk[2] + e1*fk[5] + e2*fk[8];
        float dot = p0*d0 + p1*d1 + p2*d2;
        if (dot < 0.f) {
            float s2 = dot / (d0*d0 + d1*d1 + d2*d2 + VEPS);
            p0 -= s2*d0; p1 -= s2*d1; p2 -= s2*d2;
        }
        a0 += p0; a1 += p1; a2 += p2;
    }
    size_t bn = (size_t)b*Nc + n0 + ln;
    const float inv = 1.f / (float)Kc;
    g_bufA[(bn*3 + 0)*64 + c] = a0 * inv;
    g_bufA[(bn*3 + 1)*64 + c] = a1 * inv;
    g_bufA[(bn*3 + 2)*64 + c] = a2 * inv;
}

// --------------------------- finalize stats ---------------------------------
__global__ void finalize_stats(int which, int C, float cnt) {
    const float* s = (which == 1) ? g_s1 : (which == 2) ? g_s2
                   : (which == 3) ? g_s3 : g_s4;
    int c = threadIdx.x;
    if (c >= C) return;
    float mu  = s[c] / cnt;
    float var = s[C + c] / cnt - mu*mu;
    g_mu[c]   = mu;
    g_rstd[c] = rsqrtf(var + BNEPS);
}

// --------------------------- layers 2-4: p/d GEMM + norm stats --------------
// h layout: [(bn*3+comp)*CIN + c].  Block: 16 bn rows (48 matrix rows) x COUT.
template<int COUT, int SRC, int WHICH>
__global__ __launch_bounds__(256) void gemm_pd(const float* __restrict__ W,
                                               const float* __restrict__ D) {
    const int CIN = 64;
    const float* __restrict__ h = (SRC == 0) ? g_bufA : g_bufB;
    float* sums = (WHICH == 2) ? g_s2 : (WHICH == 3) ? g_s3 : g_s4;

    int bn0 = blockIdx.x * 16;
    int tid = threadIdx.x;
    int ridx = tid >> 4;      // 0..15 -> bn row
    int cidx = tid & 15;
    const int CJ = COUT / 16;

    float ap[3][CJ], ad[3][CJ];
    #pragma unroll
    for (int c2 = 0; c2 < 3; c2++)
        #pragma unroll
        for (int j = 0; j < CJ; j++) { ap[c2][j] = 0.f; ad[c2][j] = 0.f; }

    __shared__ float hs[48][33];
    __shared__ float ws[COUT][33];
    __shared__ float ds_[COUT][33];

    for (int k0 = 0; k0 < CIN; k0 += 32) {
        for (int e = tid; e < 48*32; e += 256) {
            int r = e >> 5, kk = e & 31;
            hs[r][kk] = h[((size_t)bn0*3 + r)*CIN + k0 + kk];
        }
        for (int e = tid; e < COUT*32; e += 256) {
            int cc = e >> 5, kk = e & 31;
            ws[cc][kk]  = W[cc*CIN + k0 + kk];
            ds_[cc][kk] = D[cc*CIN + k0 + kk];
        }
        __syncthreads();
        #pragma unroll 8
        for (int kk = 0; kk < 32; kk++) {
            float h0 = hs[ridx*3 + 0][kk];
            float h1 = hs[ridx*3 + 1][kk];
            float h2 = hs[ridx*3 + 2][kk];
            #pragma unroll
            for (int j = 0; j < CJ; j++) {
                int cc = cidx + 16*j;
                float w = ws[cc][kk], dd = ds_[cc][kk];
                ap[0][j] += h0*w;  ap[1][j] += h1*w;  ap[2][j] += h2*w;
                ad[0][j] += h0*dd; ad[1][j] += h1*dd; ad[2][j] += h2*dd;
            }
        }
        __syncthreads();
    }

    __shared__ float ssum[COUT], ssum2[COUT];
    if (tid < COUT) { ssum[tid] = 0.f; ssum2[tid] = 0.f; }
    __syncthreads();

    size_t row = ((size_t)bn0 + ridx) * 3;
    #pragma unroll
    for (int j = 0; j < CJ; j++) {
        int cc = cidx + 16*j;
        float nr = sqrtf(ap[0][j]*ap[0][j] + ap[1][j]*ap[1][j] + ap[2][j]*ap[2][j]) + VEPS;
        atomicAdd(&ssum[cc], nr);
        atomicAdd(&ssum2[cc], nr*nr);
        g_p[(row + 0)*COUT + cc] = ap[0][j];
        g_p[(row + 1)*COUT + cc] = ap[1][j];
        g_p[(row + 2)*COUT + cc] = ap[2][j];
        g_d[(row + 0)*COUT + cc] = ad[0][j];
        g_d[(row + 1)*COUT + cc] = ad[1][j];
        g_d[(row + 2)*COUT + cc] = ad[2][j];
    }
    __syncthreads();
    if (tid < COUT) {
        atomicAdd(&sums[tid], ssum[tid]);
        atomicAdd(&sums[COUT + tid], ssum2[tid]);
    }
}

// --------------------------- apply BN + VN-leaky -----------------------------
template<int COUT, int DST>
__global__ __launch_bounds__(256) void apply_bn_leaky(const float* __restrict__ ga,
                                                      const float* __restrict__ be) {
    float* __restrict__ hout = (DST == 0) ? g_bufA : g_bufB;
    int i = blockIdx.x * 256 + threadIdx.x;
    if (i >= BN * COUT) return;
    int bn = i / COUT, c = i % COUT;
    size_t r = (size_t)bn * 3;
    float p0 = g_p[(r+0)*COUT + c], p1 = g_p[(r+1)*COUT + c], p2 = g_p[(r+2)*COUT + c];
    float nr = sqrtf(p0*p0 + p1*p1 + p2*p2) + VEPS;
    float sc = (ga[c]*(nr - g_mu[c])*g_rstd[c] + be[c]) / nr;
    p0 *= sc; p1 *= sc; p2 *= sc;
    float d0 = g_d[(r+0)*COUT + c], d1 = g_d[(r+1)*COUT + c], d2 = g_d[(r+2)*COUT + c];
    float dot = p0*d0 + p1*d1 + p2*d2;
    if (dot < 0.f) {
        float s2 = dot / (d0*d0 + d1*d1 + d2*d2 + VEPS);
        p0 -= s2*d0; p1 -= s2*d1; p2 -= s2*d2;
    }
    hout[(r+0)*COUT + c] = p0;
    hout[(r+1)*COUT + c] = p1;
    hout[(r+2)*COUT + c] = p2;
}

// --------------------------- conv5 fused (GEMM + stats + mean) ---------------
// v = h4 @ W5^T (CIN=128), accumulate Σv, Σv/||v|| per (b,c,comp) and
// Σ||v||, Σ||v||² per c.  Block: 32 bn rows x 64 channels.
__global__ __launch_bounds__(256) void conv5_kernel(const float* __restrict__ W5) {
    const int CIN = 128;
    int bn0 = blockIdx.x * 32;
    int c0  = blockIdx.y * 64;
    int tid = threadIdx.x;
    int rg   = tid >> 4;       // 0..15: bn rows rg*2, rg*2+1
    int cidx = tid & 15;       // c = c0 + cidx + 16*j, j<4

    float acc[2][3][4];
    #pragma unroll
    for (int a = 0; a < 2; a++)
        #pragma unroll
        for (int c2 = 0; c2 < 3; c2++)
            #pragma unroll
            for (int j = 0; j < 4; j++) acc[a][c2][j] = 0.f;

    __shared__ union {
        struct { float hs[96][33]; float ws[64][33]; } g;
        struct { float vsm[96][65]; float insm[32][64]; } s;
    } sm;
    __shared__ float s_n[64], s_n2[64];

    for (int k0 = 0; k0 < CIN; k0 += 32) {
        for (int e = tid; e < 96*32; e += 256) {
            int r = e >> 5, kk = e & 31;
            sm.g.hs[r][kk] = g_bufB[((size_t)bn0*3 + r)*CIN + k0 + kk];
        }
        for (int e = tid; e < 64*32; e += 256) {
            int cc = e >> 5, kk = e & 31;
            sm.g.ws[cc][kk] = W5[(size_t)(c0 + cc)*CIN + k0 + kk];
        }
        __syncthreads();
        #pragma unroll 8
        for (int kk = 0; kk < 32; kk++) {
            float hr[2][3];
            #pragma unroll
            for (int rt = 0; rt < 2; rt++)
                #pragma unroll
                for (int c2 = 0; c2 < 3; c2++)
                    hr[rt][c2] = sm.g.hs[(rg*2 + rt)*3 + c2][kk];
            #pragma unroll
            for (int j = 0; j < 4; j++) {
                float w = sm.g.ws[cidx + 16*j][kk];
                #pragma unroll
                for (int rt = 0; rt < 2; rt++) {
                    acc[rt][0][j] += hr[rt][0]*w;
                    acc[rt][1][j] += hr[rt][1]*w;
                    acc[rt][2][j] += hr[rt][2]*w;
                }
            }
        }
        __syncthreads();
    }

    if (tid < 64) { s_n[tid] = 0.f; s_n2[tid] = 0.f; }
    __syncthreads();

    // write v / 1/||v|| tiles into smem (union reuse), accumulate per-c norm sums
    #pragma unroll
    for (int rt = 0; rt < 2; rt++) {
        int r = rg*2 + rt;     // local bn 0..31
        #pragma unroll
        for (int j = 0; j < 4; j++) {
            int cc = cidx + 16*j;
            float v0 = acc[rt][0][j], v1 = acc[rt][1][j], v2 = acc[rt][2][j];
            float nr = sqrtf(v0*v0 + v1*v1 + v2*v2) + VEPS;
            sm.s.vsm[r*3 + 0][cc] = v0;
            sm.s.vsm[r*3 + 1][cc] = v1;
            sm.s.vsm[r*3 + 2][cc] = v2;
            sm.s.insm[r][cc] = 1.f / nr;
            atomicAdd(&s_n[cc], nr);
            atomicAdd(&s_n2[cc], nr*nr);
        }
    }
    __syncthreads();

    if (tid < 192) {
        int cc = tid & 63, comp = tid >> 6;
        float sv = 0.f, svn = 0.f;
        #pragma unroll 8
        for (int r = 0; r < 32; r++) {
            float v = sm.s.vsm[r*3 + comp][cc];
            sv  += v;
            svn += v * sm.s.insm[r][cc];
        }
        int b = bn0 / Nc;      // 32 | 4096, blocks never straddle batches
        int gi = (b*1024 + c0 + cc)*3 + comp;
        atomicAdd(&g_sumv[gi],  sv);
        atomicAdd(&g_sumvn[gi], svn);
    }
    if (tid < 64) {
        atomicAdd(&g_s5[c0 + tid],        s_n[tid]);
        atomicAdd(&g_s5[1024 + c0 + tid], s_n2[tid]);
    }
}

// --------------------------- final output ------------------------------------
__global__ void final_out(const float* __restrict__ g5, const float* __restrict__ b5,
                          float* __restrict__ out) {
    int c = blockIdx.x * 256 + threadIdx.x;
    if (c >= 1024) return;
    float mu  = g_s5[c]        * (1.f / (float)BN);
    float var = g_s5[1024 + c] * (1.f / (float)BN) - mu*mu;
    float rs  = rsqrtf(var + BNEPS);
    float a   = g5[c] * rs;                 // gamma * rstd
    float t   = a * mu - b5[c];             // gamma*mu*rstd - beta
    #pragma unroll
    for (int b = 0; b < Bc; b++)
        #pragma unroll
        for (int comp = 0; comp < 3; comp++) {
            int gi = (b*1024 + c)*3 + comp;
            out[gi] = a * (g_sumv[gi] * (1.f/(float)Nc))
                    - t * (g_sumvn[gi] * (1.f/(float)Nc));
        }
}

// ---------------------------------------------------------------------------
extern "C" void kernel_launch(void* const* d_in, const int* in_sizes, int n_in,
                              void* d_out, int out_size) {
    const float* x  = (const float*)d_in[0];
    const float* W1 = (const float*)d_in[1];
    const float* D1 = (const float*)d_in[2];
    const float* g1 = (const float*)d_in[3];
    const float* b1 = (const float*)d_in[4];
    const float* W2 = (const float*)d_in[5];
    const float* D2 = (const float*)d_in[6];
    const float* g2 = (const float*)d_in[7];
    const float* b2 = (const float*)d_in[8];
    const float* W3 = (const float*)d_in[9];
    const float* D3 = (const float*)d_in[10];
    const float* g3 = (const float*)d_in[11];
    const float* b3 = (const float*)d_in[12];
    const float* W4 = (const float*)d_in[13];
    const float* D4 = (const float*)d_in[14];
    const float* g4 = (const float*)d_in[15];
    const float* b4 = (const float*)d_in[16];
    const float* W5 = (const float*)d_in[17];
    const float* g5 = (const float*)d_in[18];
    const float* b5 = (const float*)d_in[19];
    float* out = (float*)d_out;

    zero_stats<<<48, 256>>>();
    knn_kernel<<<dim3(Nc/2, Bc), 256>>>(x);

    // block1: edge feat -> 64, pool over K
    block1_stats<<<dim3(Nc/2, Bc), 128>>>(x, W1);
    finalize_stats<<<1, 64>>>(1, 64, (float)(Bc*Nc*Kc));
    block1_apply<<<dim3(Nc/2, Bc), 128>>>(x, W1, D1, g1, b1);

    // layer2: A -> B  (64 -> 64)
    gemm_pd<64, 0, 2><<<BN/16, 256>>>(W2, D2);
    finalize_stats<<<1, 64>>>(2, 64, (float)BN);
    apply_bn_leaky<64, 1><<<(BN*64 + 255)/256, 256>>>(g2, b2);

    // layer3: B -> A  (64 -> 64)
    gemm_pd<64, 1, 3><<<BN/16, 256>>>(W3, D3);
    finalize_stats<<<1, 64>>>(3, 64, (float)BN);
    apply_bn_leaky<64, 0><<<(BN*64 + 255)/256, 256>>>(g3, b3);

    // layer4: A -> B  (64 -> 128)
    gemm_pd<128, 0, 4><<<BN/16, 256>>>(W4, D4);
    finalize_stats<<<1, 128>>>(4, 128, (float)BN);
    apply_bn_leaky<128, 1><<<(BN*128 + 255)/256, 256>>>(g4, b4);

    // conv5 + bn5 + global mean, fully fused
    conv5_kernel<<<dim3(BN/32, 16), 256>>>(W5);
    final_out<<<4, 256>>>(g5, b5, out);
}